// round 16
// baseline (speedup 1.0000x reference)
#include <cuda_runtime.h>
#include <cuda_bf16.h>
#include <cuda_fp16.h>
#include <stdint.h>

// VQ-VAE quantization. R16 = R15 (163.8us, validated rel_err==0.0) with the
// identity output section out[SEC..2SEC)=x offloaded to a copy-engine memcpy
// on a forked capture stream (runs concurrently with the compute kernels);
// the kernel epilogue drops those stores. All decision/rounding arithmetic
// byte-identical to R15.

#define BATCH 64
#define DIM   256
#define KCB   512
#define HWSZ  1024
#define NPOS  65536
#define TM    128
#define SEC   ((size_t)BATCH * DIM * HWSZ)
#define APITCH 528
#define SPITCH 1040
#define EPITCH 257
#define STP    132
#define STBYTES (32 * STP * 4)
#define BBUF   33792
#define FLAG_M 1e-3f
#define CAND_M 1.6e-3f

__device__ float d_enorm[KCB];
__device__ __nv_bfloat16 d_ebf[KCB * DIM];

__device__ __forceinline__ uint32_t smem_u32(const void* p) {
    uint32_t a;
    asm("{ .reg .u64 t; cvta.to.shared.u64 t, %1; cvt.u32.u64 %0, t; }"
        : "=r"(a) : "l"(p));
    return a;
}
__device__ __forceinline__ void ldsm4(uint32_t r[4], uint32_t addr) {
    asm volatile("ldmatrix.sync.aligned.m8n8.x4.shared.b16 {%0,%1,%2,%3}, [%4];"
                 : "=r"(r[0]), "=r"(r[1]), "=r"(r[2]), "=r"(r[3]) : "r"(addr));
}
__device__ __forceinline__ void mma16816(float c[4], const uint32_t a[4],
                                         uint32_t b0, uint32_t b1) {
    asm volatile("mma.sync.aligned.m16n8k16.row.col.f32.bf16.bf16.f32 "
                 "{%0,%1,%2,%3}, {%4,%5,%6,%7}, {%8,%9}, {%0,%1,%2,%3};"
                 : "+f"(c[0]), "+f"(c[1]), "+f"(c[2]), "+f"(c[3])
                 : "r"(a[0]), "r"(a[1]), "r"(a[2]), "r"(a[3]), "r"(b0), "r"(b1));
}
#define CPA16(dst, src) \
    asm volatile("cp.async.cg.shared.global [%0], [%1], 16;" \
                 :: "r"(dst), "l"(src) : "memory")
#define CPA_COMMIT() asm volatile("cp.async.commit_group;" ::: "memory")
#define CPA_WAIT1()  asm volatile("cp.async.wait_group 1;" ::: "memory")

// ---------------- emb prep (validated) ----------------
__global__ void prep_e(const float* __restrict__ emb) {
    const int k = blockIdx.x * 32 + threadIdx.x;
    if (k >= KCB) return;
    const float4* e4 = (const float4*)(emb + (size_t)k * DIM);
    uint32_t* eb = ((uint32_t*)d_ebf) + (size_t)k * (DIM / 2);
    float acc = 0.f;
    for (int jj = 0; jj < 8; ++jj) {
        float4 v[8];
        #pragma unroll
        for (int q = 0; q < 8; ++q) v[q] = e4[jj * 8 + q];
        #pragma unroll
        for (int q = 0; q < 8; ++q) {
            const int j = jj * 8 + q;
            acc = __fadd_rn(acc, __fmul_rn(v[q].x, v[q].x));
            acc = __fadd_rn(acc, __fmul_rn(v[q].y, v[q].y));
            acc = __fadd_rn(acc, __fmul_rn(v[q].z, v[q].z));
            acc = __fadd_rn(acc, __fmul_rn(v[q].w, v[q].w));
            eb[2 * j] = (uint32_t)__bfloat16_as_ushort(__float2bfloat16(v[q].x)) |
                        ((uint32_t)__bfloat16_as_ushort(__float2bfloat16(v[q].y)) << 16);
            eb[2 * j + 1] = (uint32_t)__bfloat16_as_ushort(__float2bfloat16(v[q].z)) |
                            ((uint32_t)__bfloat16_as_ushort(__float2bfloat16(v[q].w)) << 16);
        }
    }
    d_enorm[k] = acc;
}

// ---------------- fused main (R15, epilogue minus identity section) --------
__global__ __launch_bounds__(512, 1) void vq_fused(const float* __restrict__ x,
                                                   const float* __restrict__ emb,
                                                   float* __restrict__ out) {
    extern __shared__ char dsm[];
    __shared__ float en_s[KCB];
    __shared__ float zn_s[TM];
    __shared__ float m1s[TM][2], m2s[TM][2];
    __shared__ int ks_[TM][2];
    __shared__ int idx_s[TM];
    __shared__ int flist[TM];
    __shared__ int nflag;

    const int t   = threadIdx.x;
    const int wid = t >> 5;
    const int l   = t & 31;
    const int p0  = blockIdx.x * TM;
    const int b   = p0 >> 10;
    const int pb0 = p0 & 1023;

    char* Bp[2] = {dsm, dsm + BBUF};
    char* SC = dsm + 2 * BBUF;
    char* Ap = SC;
    char* STG0 = SC + 68608;
    const uint32_t Baddr[2] = {smem_u32(Bp[0]), smem_u32(Bp[1])};
    const uint32_t Aaddr = smem_u32(Ap);

    en_s[t] = d_enorm[t];
    if (t == 0) nflag = 0;

    // ---- B prefetch chunks 0,1 up front ----
    #pragma unroll
    for (int it = 0; it < 4; ++it) {
        int i = t + it * 512, row = i >> 5, seg = i & 31;
        CPA16(Baddr[0] + row * APITCH + seg * 16,
              (const char*)d_ebf + (size_t)row * 512 + seg * 16);
    }
    CPA_COMMIT();
    #pragma unroll
    for (int it = 0; it < 4; ++it) {
        int i = t + it * 512, row = i >> 5, seg = i & 31;
        CPA16(Baddr[1] + row * APITCH + seg * 16,
              (const char*)d_ebf + (size_t)(64 + row) * 512 + seg * 16);
    }
    CPA_COMMIT();

    // ---- A-build: float4 staged, double-buffered, one barrier per chunk ----
    {
        float* stb[2] = {(float*)STG0, (float*)(STG0 + STBYTES)};
        float zacc = 0.f;
        const float* gx = x + (size_t)b * DIM * HWSZ + pb0;
        float4 rg[2];
        #pragma unroll
        for (int it = 0; it < 2; ++it) {
            int s = t + it * 512, r = s >> 5, q = s & 31;
            rg[it] = __ldg((const float4*)&gx[(size_t)r * HWSZ + 4 * q]);
        }
        for (int ch = 0; ch < 8; ++ch) {
            float* st = stb[ch & 1];
            #pragma unroll
            for (int it = 0; it < 2; ++it) {
                int s = t + it * 512, r = s >> 5, q = s & 31;
                *(float4*)&st[r * STP + 4 * q] = rg[it];
            }
            __syncthreads();
            if (ch < 7) {
                #pragma unroll
                for (int it = 0; it < 2; ++it) {
                    int s = t + it * 512, r = s >> 5, q = s & 31;
                    rg[it] = __ldg((const float4*)
                                   &gx[(size_t)((ch + 1) * 32 + r) * HWSZ + 4 * q]);
                }
            }
            if (t < TM) {                      // znorm: sequential in d (validated)
                #pragma unroll 8
                for (int r = 0; r < 32; ++r) {
                    float v = st[r * STP + t];
                    zacc = __fadd_rn(zacc, __fmul_rn(v, v));
                }
            }
            {                                  // pack bf16 into A[pos][d] (validated)
                const int pos = t >> 2, sub = t & 3;
                uint32_t pk[4];
                #pragma unroll
                for (int j = 0; j < 4; ++j) {
                    float v0 = st[(sub * 8 + 2 * j) * STP + pos];
                    float v1 = st[(sub * 8 + 2 * j + 1) * STP + pos];
                    pk[j] = (uint32_t)__bfloat16_as_ushort(__float2bfloat16(v0)) |
                            ((uint32_t)__bfloat16_as_ushort(__float2bfloat16(v1)) << 16);
                }
                *(uint4*)(Ap + pos * APITCH + ch * 64 + sub * 16) =
                    make_uint4(pk[0], pk[1], pk[2], pk[3]);
            }
        }
        if (t < TM) zn_s[t] = zacc;
    }
    __syncthreads();

    const int m0 = (wid & 7) * 16;
    const int nb = (wid >> 3) * 32;
    uint32_t af[16][4];
    {
        uint32_t base = Aaddr + (uint32_t)(m0 + (l & 15)) * APITCH + (uint32_t)(l >> 4) * 16;
        #pragma unroll
        for (int ks = 0; ks < 16; ++ks) ldsm4(af[ks], base + ks * 32);
    }

    float min1a = 1e30f, min2a = 1e30f, min1b = 1e30f, min2b = 1e30f;
    int kma = 0, kmb = 0;
    const int row0 = m0 + (l >> 2);

    for (int nc = 0; nc < 8; ++nc) {
        CPA_WAIT1();
        __syncthreads();

        const uint32_t bbase = Baddr[nc & 1] + (uint32_t)(nb + (l & 7)) * APITCH
                             + (uint32_t)(l >> 3) * 16;
        for (int nt = 0; nt < 4; ++nt) {
            float c[4] = {0.f, 0.f, 0.f, 0.f};
            const uint32_t baddr = bbase + (uint32_t)nt * 8 * APITCH;
            #pragma unroll
            for (int ksp = 0; ksp < 8; ++ksp) {
                uint32_t br[4];
                ldsm4(br, baddr + ksp * 64);
                mma16816(c, af[2 * ksp],     br[0], br[1]);
                mma16816(c, af[2 * ksp + 1], br[2], br[3]);
            }
            const int kb = nc * 64 + nb + nt * 8 + ((l & 3) << 1);
            const float en0 = en_s[kb], en1 = en_s[kb + 1];
            float s0 = fmaf(-2.f, c[0], en0), s1 = fmaf(-2.f, c[1], en1);
            float s2 = fmaf(-2.f, c[2], en0), s3 = fmaf(-2.f, c[3], en1);
            *(__half2*)(SC + row0 * SPITCH + kb * 2)       = __floats2half2_rn(s0, s1);
            *(__half2*)(SC + (row0 + 8) * SPITCH + kb * 2) = __floats2half2_rn(s2, s3);
            if (s0 < min1a) { min2a = min1a; min1a = s0; kma = kb; }
            else if (s0 < min2a) min2a = s0;
            if (s1 < min1a) { min2a = min1a; min1a = s1; kma = kb + 1; }
            else if (s1 < min2a) min2a = s1;
            if (s2 < min1b) { min2b = min1b; min1b = s2; kmb = kb; }
            else if (s2 < min2b) min2b = s2;
            if (s3 < min1b) { min2b = min1b; min1b = s3; kmb = kb + 1; }
            else if (s3 < min2b) min2b = s3;
        }
        __syncthreads();
        if (nc + 2 < 8) {
            #pragma unroll
            for (int it = 0; it < 4; ++it) {
                int i = t + it * 512, row = i >> 5, seg = i & 31;
                CPA16(Baddr[nc & 1] + row * APITCH + seg * 16,
                      (const char*)d_ebf + (size_t)((nc + 2) * 64 + row) * 512 + seg * 16);
            }
        }
        CPA_COMMIT();
    }

    // quad merge within warp (validated)
    #pragma unroll
    for (int msk = 1; msk <= 2; msk <<= 1) {
        float o1 = __shfl_xor_sync(0xFFFFFFFFu, min1a, msk);
        float o2 = __shfl_xor_sync(0xFFFFFFFFu, min2a, msk);
        int   ok = __shfl_xor_sync(0xFFFFFFFFu, kma,  msk);
        float hi = fmaxf(min1a, o1);
        if (o1 < min1a) { min1a = o1; kma = ok; }
        min2a = fminf(fminf(min2a, o2), hi);
        o1 = __shfl_xor_sync(0xFFFFFFFFu, min1b, msk);
        o2 = __shfl_xor_sync(0xFFFFFFFFu, min2b, msk);
        ok = __shfl_xor_sync(0xFFFFFFFFu, kmb,  msk);
        hi = fmaxf(min1b, o1);
        if (o1 < min1b) { min1b = o1; kmb = ok; }
        min2b = fminf(fminf(min2b, o2), hi);
    }
    const int wg = wid >> 3;
    if ((l & 3) == 0) {
        const int pa = m0 + (l >> 2);
        m1s[pa][wg] = min1a;  m2s[pa][wg] = min2a;  ks_[pa][wg] = kma;
        m1s[pa + 8][wg] = min1b;  m2s[pa + 8][wg] = min2b;  ks_[pa + 8][wg] = kmb;
    }
    __syncthreads();

    if (t < TM) {
        float a1 = m1s[t][0], b1 = m1s[t][1];
        float lo = fminf(a1, b1), hi = fmaxf(a1, b1);
        int kf = (b1 < a1) ? ks_[t][1] : ks_[t][0];
        float m2 = fminf(fminf(m2s[t][0], m2s[t][1]), hi);
        idx_s[t] = kf;
        if (m2 - lo <= FLAG_M) { int sl = atomicAdd(&nflag, 1); flist[sl] = t; }
    }
    __syncthreads();

    // ---- exact arbitration (validated), warp per flagged position ----
    const int nf = nflag;
    for (int i = wid; i < nf; i += 16) {
        const int pl = flist[i];
        const int pb = pb0 + pl;

        const uint4* rowq = (const uint4*)(SC + pl * SPITCH);
        __half2 hh[8];
        *(uint4*)&hh[0] = rowq[l * 2];
        *(uint4*)&hh[4] = rowq[l * 2 + 1];
        float s[16];
        #pragma unroll
        for (int j = 0; j < 8; ++j) {
            float2 f = __half22float2(hh[j]);
            s[2 * j] = f.x;  s[2 * j + 1] = f.y;
        }
        float smin = s[0];
        #pragma unroll
        for (int j = 1; j < 16; ++j) smin = fminf(smin, s[j]);
        #pragma unroll
        for (int m = 16; m >= 1; m >>= 1)
            smin = fminf(smin, __shfl_xor_sync(0xFFFFFFFFu, smin, m));
        const float lim = smin + CAND_M;

        const float* xc = x + (size_t)b * DIM * HWSZ + pb;
        float xv[8];
        #pragma unroll
        for (int j = 0; j < 8; ++j)
            xv[j] = __ldg(&xc[(size_t)(l * 8 + j) * HWSZ]);
        const float znv = zn_s[pl];

        unsigned long long best = ~0ull;
        for (int c = 0; c < 16; ++c) {
            unsigned mask = __ballot_sync(0xFFFFFFFFu, s[c] <= lim);
            while (mask) {
                int src = __ffs(mask) - 1;
                mask &= mask - 1;
                const int k = src * 16 + c;
                const float4* er = (const float4*)(emb + (size_t)k * DIM) + l * 2;
                float4 e0 = er[0], e1 = er[1];
                float part = 0.f;
                part = fmaf(e0.x, xv[0], part);  part = fmaf(e0.y, xv[1], part);
                part = fmaf(e0.z, xv[2], part);  part = fmaf(e0.w, xv[3], part);
                part = fmaf(e1.x, xv[4], part);  part = fmaf(e1.y, xv[5], part);
                part = fmaf(e1.z, xv[6], part);  part = fmaf(e1.w, xv[7], part);
                #pragma unroll
                for (int m = 16; m >= 1; m >>= 1)
                    part += __shfl_xor_sync(0xFFFFFFFFu, part, m);
                float dist = __fadd_rn(__fadd_rn(znv, en_s[k]),
                                       __fmul_rn(-2.f, part));
                unsigned u = __float_as_uint(dist);
                u = (u & 0x80000000u) ? ~u : (u | 0x80000000u);
                unsigned long long key = ((unsigned long long)u << 32) | (unsigned)k;
                if (key < best) best = key;
            }
        }
        if (l == 0) idx_s[pl] = (int)(best & 0xFFFFFFFFull);
    }
    __syncthreads();

    // ---- gather e-rows to smem ----
    float* es = (float*)SC;
    for (int r = wid; r < TM; r += 16) {
        const float* er = emb + (size_t)idx_s[r] * DIM;
        #pragma unroll
        for (int j = 0; j < 8; ++j)
            es[r * EPITCH + j * 32 + l] = __ldg(&er[j * 32 + l]);
    }
    __syncthreads();

    // ---- epilogue: out0 + out2 only (out1 handled by copy engine) ----
    {
        const int pp = t & 63;
        const int dh = t >> 6;
        const size_t gb = (size_t)b * DIM * HWSZ + pb0 + 2 * pp;
        const float* e0 = es + (2 * pp) * EPITCH;
        const float* e1 = es + (2 * pp + 1) * EPITCH;
        #pragma unroll 4
        for (int d = dh * 32; d < dh * 32 + 32; ++d) {
            size_t off = gb + (size_t)d * HWSZ;
            float2 z2 = __ldg((const float2*)&x[off]);
            float2 v2 = make_float2(e0[d], e1[d]);
            float2 o2 = make_float2(__fadd_rn(z2.x, __fadd_rn(v2.x, -z2.x)),
                                    __fadd_rn(z2.y, __fadd_rn(v2.y, -z2.y)));
            *(float2*)&out[off]           = o2;
            *(float2*)&out[off + 2 * SEC] = v2;
        }
    }
}

extern "C" void kernel_launch(void* const* d_in, const int* in_sizes, int n_in,
                              void* d_out, int out_size) {
    const float* x   = (const float*)d_in[0];
    const float* emb = (const float*)d_in[1];
    float* out = (float*)d_out;
    (void)in_sizes; (void)n_in; (void)out_size;

    static int inited = 0;
    static cudaStream_t s2;
    static cudaEvent_t ev_fork, ev_join;
    const int dyn = 2 * BBUF + 128 * SPITCH;   // 200704 B
    if (!inited) {
        cudaFuncSetAttribute(vq_fused, cudaFuncAttributeMaxDynamicSharedMemorySize, dyn);
        cudaStreamCreateWithFlags(&s2, cudaStreamNonBlocking);
        cudaEventCreateWithFlags(&ev_fork, cudaEventDisableTiming);
        cudaEventCreateWithFlags(&ev_join, cudaEventDisableTiming);
        inited = 1;
    }

    // fork: copy engine writes the identity section concurrently with compute
    cudaEventRecord(ev_fork, 0);
    cudaStreamWaitEvent(s2, ev_fork, 0);
    cudaMemcpyAsync(out + SEC, x, SEC * sizeof(float),
                    cudaMemcpyDeviceToDevice, s2);
    cudaEventRecord(ev_join, s2);

    prep_e<<<16, 32>>>(emb);
    vq_fused<<<NPOS / TM, 512, dyn>>>(x, emb, out);

    // join: downstream work on the main stream sees the copy complete
    cudaStreamWaitEvent(0, ev_join, 0);
}

// round 17
// speedup vs baseline: 1.4144x; 1.4144x over previous
#include <cuda_runtime.h>
#include <cuda_bf16.h>
#include <cuda_fp16.h>
#include <stdint.h>

// VQ-VAE quantization. R17 = R16's kernel (144.7us, validated rel_err==0.0,
// epilogue writes out0/out2 only) + out1 (= x verbatim) written during the
// A-build phase straight from the staging registers (STG.128, overlapped with
// the A-build's LDG latency). No streams / memcpy (R16's serial-copy regression
// reverted). All decision/rounding arithmetic byte-identical to R15/R16.

#define BATCH 64
#define DIM   256
#define KCB   512
#define HWSZ  1024
#define NPOS  65536
#define TM    128
#define SEC   ((size_t)BATCH * DIM * HWSZ)
#define APITCH 528
#define SPITCH 1040
#define EPITCH 257
#define STP    132
#define STBYTES (32 * STP * 4)
#define BBUF   33792
#define FLAG_M 1e-3f
#define CAND_M 1.6e-3f

__device__ float d_enorm[KCB];
__device__ __nv_bfloat16 d_ebf[KCB * DIM];

__device__ __forceinline__ uint32_t smem_u32(const void* p) {
    uint32_t a;
    asm("{ .reg .u64 t; cvta.to.shared.u64 t, %1; cvt.u32.u64 %0, t; }"
        : "=r"(a) : "l"(p));
    return a;
}
__device__ __forceinline__ void ldsm4(uint32_t r[4], uint32_t addr) {
    asm volatile("ldmatrix.sync.aligned.m8n8.x4.shared.b16 {%0,%1,%2,%3}, [%4];"
                 : "=r"(r[0]), "=r"(r[1]), "=r"(r[2]), "=r"(r[3]) : "r"(addr));
}
__device__ __forceinline__ void mma16816(float c[4], const uint32_t a[4],
                                         uint32_t b0, uint32_t b1) {
    asm volatile("mma.sync.aligned.m16n8k16.row.col.f32.bf16.bf16.f32 "
                 "{%0,%1,%2,%3}, {%4,%5,%6,%7}, {%8,%9}, {%0,%1,%2,%3};"
                 : "+f"(c[0]), "+f"(c[1]), "+f"(c[2]), "+f"(c[3])
                 : "r"(a[0]), "r"(a[1]), "r"(a[2]), "r"(a[3]), "r"(b0), "r"(b1));
}
#define CPA16(dst, src) \
    asm volatile("cp.async.cg.shared.global [%0], [%1], 16;" \
                 :: "r"(dst), "l"(src) : "memory")
#define CPA_COMMIT() asm volatile("cp.async.commit_group;" ::: "memory")
#define CPA_WAIT1()  asm volatile("cp.async.wait_group 1;" ::: "memory")

// ---------------- emb prep (validated) ----------------
__global__ void prep_e(const float* __restrict__ emb) {
    const int k = blockIdx.x * 32 + threadIdx.x;
    if (k >= KCB) return;
    const float4* e4 = (const float4*)(emb + (size_t)k * DIM);
    uint32_t* eb = ((uint32_t*)d_ebf) + (size_t)k * (DIM / 2);
    float acc = 0.f;
    for (int jj = 0; jj < 8; ++jj) {
        float4 v[8];
        #pragma unroll
        for (int q = 0; q < 8; ++q) v[q] = e4[jj * 8 + q];
        #pragma unroll
        for (int q = 0; q < 8; ++q) {
            const int j = jj * 8 + q;
            acc = __fadd_rn(acc, __fmul_rn(v[q].x, v[q].x));
            acc = __fadd_rn(acc, __fmul_rn(v[q].y, v[q].y));
            acc = __fadd_rn(acc, __fmul_rn(v[q].z, v[q].z));
            acc = __fadd_rn(acc, __fmul_rn(v[q].w, v[q].w));
            eb[2 * j] = (uint32_t)__bfloat16_as_ushort(__float2bfloat16(v[q].x)) |
                        ((uint32_t)__bfloat16_as_ushort(__float2bfloat16(v[q].y)) << 16);
            eb[2 * j + 1] = (uint32_t)__bfloat16_as_ushort(__float2bfloat16(v[q].z)) |
                            ((uint32_t)__bfloat16_as_ushort(__float2bfloat16(v[q].w)) << 16);
        }
    }
    d_enorm[k] = acc;
}

// ---------------- fused main ----------------
__global__ __launch_bounds__(512, 1) void vq_fused(const float* __restrict__ x,
                                                   const float* __restrict__ emb,
                                                   float* __restrict__ out) {
    extern __shared__ char dsm[];
    __shared__ float en_s[KCB];
    __shared__ float zn_s[TM];
    __shared__ float m1s[TM][2], m2s[TM][2];
    __shared__ int ks_[TM][2];
    __shared__ int idx_s[TM];
    __shared__ int flist[TM];
    __shared__ int nflag;

    const int t   = threadIdx.x;
    const int wid = t >> 5;
    const int l   = t & 31;
    const int p0  = blockIdx.x * TM;
    const int b   = p0 >> 10;
    const int pb0 = p0 & 1023;

    char* Bp[2] = {dsm, dsm + BBUF};
    char* SC = dsm + 2 * BBUF;
    char* Ap = SC;
    char* STG0 = SC + 68608;
    const uint32_t Baddr[2] = {smem_u32(Bp[0]), smem_u32(Bp[1])};
    const uint32_t Aaddr = smem_u32(Ap);

    en_s[t] = d_enorm[t];
    if (t == 0) nflag = 0;

    // ---- B prefetch chunks 0,1 up front ----
    #pragma unroll
    for (int it = 0; it < 4; ++it) {
        int i = t + it * 512, row = i >> 5, seg = i & 31;
        CPA16(Baddr[0] + row * APITCH + seg * 16,
              (const char*)d_ebf + (size_t)row * 512 + seg * 16);
    }
    CPA_COMMIT();
    #pragma unroll
    for (int it = 0; it < 4; ++it) {
        int i = t + it * 512, row = i >> 5, seg = i & 31;
        CPA16(Baddr[1] + row * APITCH + seg * 16,
              (const char*)d_ebf + (size_t)(64 + row) * 512 + seg * 16);
    }
    CPA_COMMIT();

    // ---- A-build: float4 staged, double-buffered, one barrier per chunk;
    //      out1 (= x verbatim) stored from the same registers ----
    {
        float* stb[2] = {(float*)STG0, (float*)(STG0 + STBYTES)};
        float zacc = 0.f;
        const float* gx = x + (size_t)b * DIM * HWSZ + pb0;
        float* go = out + SEC + (size_t)b * DIM * HWSZ + pb0;
        float4 rg[2];
        #pragma unroll
        for (int it = 0; it < 2; ++it) {
            int s = t + it * 512, r = s >> 5, q = s & 31;
            rg[it] = __ldg((const float4*)&gx[(size_t)r * HWSZ + 4 * q]);
        }
        for (int ch = 0; ch < 8; ++ch) {
            float* st = stb[ch & 1];
            #pragma unroll
            for (int it = 0; it < 2; ++it) {
                int s = t + it * 512, r = s >> 5, q = s & 31;
                *(float4*)&st[r * STP + 4 * q] = rg[it];
                *(float4*)&go[(size_t)(ch * 32 + r) * HWSZ + 4 * q] = rg[it];  // out1
            }
            __syncthreads();
            if (ch < 7) {
                #pragma unroll
                for (int it = 0; it < 2; ++it) {
                    int s = t + it * 512, r = s >> 5, q = s & 31;
                    rg[it] = __ldg((const float4*)
                                   &gx[(size_t)((ch + 1) * 32 + r) * HWSZ + 4 * q]);
                }
            }
            if (t < TM) {                      // znorm: sequential in d (validated)
                #pragma unroll 8
                for (int r = 0; r < 32; ++r) {
                    float v = st[r * STP + t];
                    zacc = __fadd_rn(zacc, __fmul_rn(v, v));
                }
            }
            {                                  // pack bf16 into A[pos][d] (validated)
                const int pos = t >> 2, sub = t & 3;
                uint32_t pk[4];
                #pragma unroll
                for (int j = 0; j < 4; ++j) {
                    float v0 = st[(sub * 8 + 2 * j) * STP + pos];
                    float v1 = st[(sub * 8 + 2 * j + 1) * STP + pos];
                    pk[j] = (uint32_t)__bfloat16_as_ushort(__float2bfloat16(v0)) |
                            ((uint32_t)__bfloat16_as_ushort(__float2bfloat16(v1)) << 16);
                }
                *(uint4*)(Ap + pos * APITCH + ch * 64 + sub * 16) =
                    make_uint4(pk[0], pk[1], pk[2], pk[3]);
            }
        }
        if (t < TM) zn_s[t] = zacc;
    }
    __syncthreads();

    const int m0 = (wid & 7) * 16;
    const int nb = (wid >> 3) * 32;
    uint32_t af[16][4];
    {
        uint32_t base = Aaddr + (uint32_t)(m0 + (l & 15)) * APITCH + (uint32_t)(l >> 4) * 16;
        #pragma unroll
        for (int ks = 0; ks < 16; ++ks) ldsm4(af[ks], base + ks * 32);
    }

    float min1a = 1e30f, min2a = 1e30f, min1b = 1e30f, min2b = 1e30f;
    int kma = 0, kmb = 0;
    const int row0 = m0 + (l >> 2);

    for (int nc = 0; nc < 8; ++nc) {
        CPA_WAIT1();
        __syncthreads();

        const uint32_t bbase = Baddr[nc & 1] + (uint32_t)(nb + (l & 7)) * APITCH
                             + (uint32_t)(l >> 3) * 16;
        for (int nt = 0; nt < 4; ++nt) {
            float c[4] = {0.f, 0.f, 0.f, 0.f};
            const uint32_t baddr = bbase + (uint32_t)nt * 8 * APITCH;
            #pragma unroll
            for (int ksp = 0; ksp < 8; ++ksp) {
                uint32_t br[4];
                ldsm4(br, baddr + ksp * 64);
                mma16816(c, af[2 * ksp],     br[0], br[1]);
                mma16816(c, af[2 * ksp + 1], br[2], br[3]);
            }
            const int kb = nc * 64 + nb + nt * 8 + ((l & 3) << 1);
            const float en0 = en_s[kb], en1 = en_s[kb + 1];
            float s0 = fmaf(-2.f, c[0], en0), s1 = fmaf(-2.f, c[1], en1);
            float s2 = fmaf(-2.f, c[2], en0), s3 = fmaf(-2.f, c[3], en1);
            *(__half2*)(SC + row0 * SPITCH + kb * 2)       = __floats2half2_rn(s0, s1);
            *(__half2*)(SC + (row0 + 8) * SPITCH + kb * 2) = __floats2half2_rn(s2, s3);
            if (s0 < min1a) { min2a = min1a; min1a = s0; kma = kb; }
            else if (s0 < min2a) min2a = s0;
            if (s1 < min1a) { min2a = min1a; min1a = s1; kma = kb + 1; }
            else if (s1 < min2a) min2a = s1;
            if (s2 < min1b) { min2b = min1b; min1b = s2; kmb = kb; }
            else if (s2 < min2b) min2b = s2;
            if (s3 < min1b) { min2b = min1b; min1b = s3; kmb = kb + 1; }
            else if (s3 < min2b) min2b = s3;
        }
        __syncthreads();
        if (nc + 2 < 8) {
            #pragma unroll
            for (int it = 0; it < 4; ++it) {
                int i = t + it * 512, row = i >> 5, seg = i & 31;
                CPA16(Baddr[nc & 1] + row * APITCH + seg * 16,
                      (const char*)d_ebf + (size_t)((nc + 2) * 64 + row) * 512 + seg * 16);
            }
        }
        CPA_COMMIT();
    }

    // quad merge within warp (validated)
    #pragma unroll
    for (int msk = 1; msk <= 2; msk <<= 1) {
        float o1 = __shfl_xor_sync(0xFFFFFFFFu, min1a, msk);
        float o2 = __shfl_xor_sync(0xFFFFFFFFu, min2a, msk);
        int   ok = __shfl_xor_sync(0xFFFFFFFFu, kma,  msk);
        float hi = fmaxf(min1a, o1);
        if (o1 < min1a) { min1a = o1; kma = ok; }
        min2a = fminf(fminf(min2a, o2), hi);
        o1 = __shfl_xor_sync(0xFFFFFFFFu, min1b, msk);
        o2 = __shfl_xor_sync(0xFFFFFFFFu, min2b, msk);
        ok = __shfl_xor_sync(0xFFFFFFFFu, kmb,  msk);
        hi = fmaxf(min1b, o1);
        if (o1 < min1b) { min1b = o1; kmb = ok; }
        min2b = fminf(fminf(min2b, o2), hi);
    }
    const int wg = wid >> 3;
    if ((l & 3) == 0) {
        const int pa = m0 + (l >> 2);
        m1s[pa][wg] = min1a;  m2s[pa][wg] = min2a;  ks_[pa][wg] = kma;
        m1s[pa + 8][wg] = min1b;  m2s[pa + 8][wg] = min2b;  ks_[pa + 8][wg] = kmb;
    }
    __syncthreads();

    if (t < TM) {
        float a1 = m1s[t][0], b1 = m1s[t][1];
        float lo = fminf(a1, b1), hi = fmaxf(a1, b1);
        int kf = (b1 < a1) ? ks_[t][1] : ks_[t][0];
        float m2 = fminf(fminf(m2s[t][0], m2s[t][1]), hi);
        idx_s[t] = kf;
        if (m2 - lo <= FLAG_M) { int sl = atomicAdd(&nflag, 1); flist[sl] = t; }
    }
    __syncthreads();

    // ---- exact arbitration (validated), warp per flagged position ----
    const int nf = nflag;
    for (int i = wid; i < nf; i += 16) {
        const int pl = flist[i];
        const int pb = pb0 + pl;

        const uint4* rowq = (const uint4*)(SC + pl * SPITCH);
        __half2 hh[8];
        *(uint4*)&hh[0] = rowq[l * 2];
        *(uint4*)&hh[4] = rowq[l * 2 + 1];
        float s[16];
        #pragma unroll
        for (int j = 0; j < 8; ++j) {
            float2 f = __half22float2(hh[j]);
            s[2 * j] = f.x;  s[2 * j + 1] = f.y;
        }
        float smin = s[0];
        #pragma unroll
        for (int j = 1; j < 16; ++j) smin = fminf(smin, s[j]);
        #pragma unroll
        for (int m = 16; m >= 1; m >>= 1)
            smin = fminf(smin, __shfl_xor_sync(0xFFFFFFFFu, smin, m));
        const float lim = smin + CAND_M;

        const float* xc = x + (size_t)b * DIM * HWSZ + pb;
        float xv[8];
        #pragma unroll
        for (int j = 0; j < 8; ++j)
            xv[j] = __ldg(&xc[(size_t)(l * 8 + j) * HWSZ]);
        const float znv = zn_s[pl];

        unsigned long long best = ~0ull;
        for (int c = 0; c < 16; ++c) {
            unsigned mask = __ballot_sync(0xFFFFFFFFu, s[c] <= lim);
            while (mask) {
                int src = __ffs(mask) - 1;
                mask &= mask - 1;
                const int k = src * 16 + c;
                const float4* er = (const float4*)(emb + (size_t)k * DIM) + l * 2;
                float4 e0 = er[0], e1 = er[1];
                float part = 0.f;
                part = fmaf(e0.x, xv[0], part);  part = fmaf(e0.y, xv[1], part);
                part = fmaf(e0.z, xv[2], part);  part = fmaf(e0.w, xv[3], part);
                part = fmaf(e1.x, xv[4], part);  part = fmaf(e1.y, xv[5], part);
                part = fmaf(e1.z, xv[6], part);  part = fmaf(e1.w, xv[7], part);
                #pragma unroll
                for (int m = 16; m >= 1; m >>= 1)
                    part += __shfl_xor_sync(0xFFFFFFFFu, part, m);
                float dist = __fadd_rn(__fadd_rn(znv, en_s[k]),
                                       __fmul_rn(-2.f, part));
                unsigned u = __float_as_uint(dist);
                u = (u & 0x80000000u) ? ~u : (u | 0x80000000u);
                unsigned long long key = ((unsigned long long)u << 32) | (unsigned)k;
                if (key < best) best = key;
            }
        }
        if (l == 0) idx_s[pl] = (int)(best & 0xFFFFFFFFull);
    }
    __syncthreads();

    // ---- gather e-rows to smem ----
    float* es = (float*)SC;
    for (int r = wid; r < TM; r += 16) {
        const float* er = emb + (size_t)idx_s[r] * DIM;
        #pragma unroll
        for (int j = 0; j < 8; ++j)
            es[r * EPITCH + j * 32 + l] = __ldg(&er[j * 32 + l]);
    }
    __syncthreads();

    // ---- epilogue: out0 + out2 (out1 already written during A-build) ----
    {
        const int pp = t & 63;
        const int dh = t >> 6;
        const size_t gb = (size_t)b * DIM * HWSZ + pb0 + 2 * pp;
        const float* e0 = es + (2 * pp) * EPITCH;
        const float* e1 = es + (2 * pp + 1) * EPITCH;
        #pragma unroll 4
        for (int d = dh * 32; d < dh * 32 + 32; ++d) {
            size_t off = gb + (size_t)d * HWSZ;
            float2 z2 = __ldg((const float2*)&x[off]);
            float2 v2 = make_float2(e0[d], e1[d]);
            float2 o2 = make_float2(__fadd_rn(z2.x, __fadd_rn(v2.x, -z2.x)),
                                    __fadd_rn(z2.y, __fadd_rn(v2.y, -z2.y)));
            *(float2*)&out[off]           = o2;
            *(float2*)&out[off + 2 * SEC] = v2;
        }
    }
}

extern "C" void kernel_launch(void* const* d_in, const int* in_sizes, int n_in,
                              void* d_out, int out_size) {
    const float* x   = (const float*)d_in[0];
    const float* emb = (const float*)d_in[1];
    float* out = (float*)d_out;
    (void)in_sizes; (void)n_in; (void)out_size;

    static int smem_set = 0;
    const int dyn = 2 * BBUF + 128 * SPITCH;   // 200704 B
    if (!smem_set) {
        cudaFuncSetAttribute(vq_fused, cudaFuncAttributeMaxDynamicSharedMemorySize, dyn);
        smem_set = 1;
    }

    prep_e<<<16, 32>>>(emb);
    vq_fused<<<NPOS / TM, 512, dyn>>>(x, emb, out);
}